// round 3
// baseline (speedup 1.0000x reference)
#include <cuda_runtime.h>
#include <cuda_bf16.h>

// Inputs (metadata order):
//   d_in[0] input_values   float32 [1024]
//   d_in[1] weight_matrix  float32 [16384*16384] row-major
//   d_in[2] biases         float32 [16384]
//   d_in[3] act_ids        int32   [16384]   0=identity 1=relu 2=softsign
//   d_in[4] input_indices  int32   [1024]
//   d_in[5] output_indices int32   [256]
// Output: float32 [256]
//
// out[o] = act( sum_i in_vals[i] * W[in_idx[i], out_idx[o]] + bias[out_idx[o]] )
//
// Single-launch design: grid = out_size * CHUNKS small CTAs (128 threads).
// Each CTA reduces one 128-row slice of one output's dot product, atomically
// accumulates into a __device__ scratch float, and the LAST-arriving CTA per
// output (arrival counter) finalizes: + bias, activation select, store to
// d_out, then resets the scratch slots so the next graph replay starts clean
// (replays are stream-ordered, so the reset cannot race the next replay).

#define CHUNK_THREADS 128
#define MAX_OUT 4096

__device__ float        g_accum[MAX_OUT];   // zero-initialized at module load
__device__ unsigned int g_count[MAX_OUT];   // zero-initialized at module load

__global__ void __launch_bounds__(CHUNK_THREADS)
fused_gather_kernel(const float* __restrict__ in_vals,
                    const float* __restrict__ W,
                    const float* __restrict__ bias,
                    const int*   __restrict__ act_ids,
                    const int*   __restrict__ in_idx,
                    const int*   __restrict__ out_idx,
                    float*       __restrict__ out,
                    int n_in, int chunks, long long N)
{
    const int c     = blockIdx.x;
    const int o     = c / chunks;           // output slot
    const int chunk = c - o * chunks;       // row-slice within the dot product
    const int t     = threadIdx.x;
    const int i     = chunk * CHUNK_THREADS + t;

    const int j = __ldg(&out_idx[o]);       // column (uniform per CTA)

    float p = 0.0f;
    if (i < n_in) {
        const long long row = (long long)__ldg(&in_idx[i]);
        p = __ldg(&in_vals[i]) * __ldg(&W[row * N + (long long)j]);
    }

    // warp reduce, then cross-warp combine (4 warps)
    #pragma unroll
    for (int off = 16; off > 0; off >>= 1)
        p += __shfl_xor_sync(0xFFFFFFFFu, p, off);

    __shared__ float sm[CHUNK_THREADS / 32];
    const int lane = t & 31;
    const int wid  = t >> 5;
    if (lane == 0) sm[wid] = p;
    __syncthreads();

    if (t == 0) {
        float v = sm[0];
        #pragma unroll
        for (int w = 1; w < CHUNK_THREADS / 32; w++) v += sm[w];

        atomicAdd(&g_accum[o], v);
        __threadfence();
        const unsigned int old = atomicAdd(&g_count[o], 1u);
        if (old == (unsigned int)(chunks - 1)) {
            // all slices for this output have landed
            __threadfence();
            const float sum   = *((volatile float*)&g_accum[o]);
            const float total = sum + __ldg(&bias[j]);
            const int   a     = __ldg(&act_ids[j]);
            const float relu  = fmaxf(total, 0.0f);
            const float ssign = total / (1.0f + fabsf(total));
            out[o] = (a == 1) ? relu : ((a == 2) ? ssign : total);
            // reset scratch for the next (stream-ordered) graph replay
            *((volatile float*)&g_accum[o])        = 0.0f;
            *((volatile unsigned int*)&g_count[o]) = 0u;
        }
    }
}

extern "C" void kernel_launch(void* const* d_in, const int* in_sizes, int n_in_args,
                              void* d_out, int out_size)
{
    const float* in_vals = (const float*)d_in[0];
    const float* W       = (const float*)d_in[1];
    const float* bias    = (const float*)d_in[2];
    const int*   act_ids = (const int*)  d_in[3];
    const int*   in_idx  = (const int*)  d_in[4];
    const int*   out_idx = (const int*)  d_in[5];
    float*       out     = (float*)      d_out;

    const int n_in = in_sizes[0];                 // 1024
    const long long N = (long long)in_sizes[2];   // 16384 (bias length)

    const int chunks = (n_in + CHUNK_THREADS - 1) / CHUNK_THREADS;  // 8

    fused_gather_kernel<<<out_size * chunks, CHUNK_THREADS>>>(
        in_vals, W, bias, act_ids, in_idx, out_idx, out, n_in, chunks, N);
}

// round 4
// speedup vs baseline: 1.4375x; 1.4375x over previous
#include <cuda_runtime.h>
#include <cuda_bf16.h>

// Inputs (metadata order):
//   d_in[0] input_values   float32 [1024]
//   d_in[1] weight_matrix  float32 [16384*16384] row-major
//   d_in[2] biases         float32 [16384]
//   d_in[3] act_ids        int32   [16384]   0=identity 1=relu 2=softsign
//   d_in[4] input_indices  int32   [1024]
//   d_in[5] output_indices int32   [256]
// Output: float32 [256]
//
// out[o] = act( sum_i in_vals[i] * W[in_idx[i], out_idx[o]] + bias[out_idx[o]] )
//
// Single launch, one CTA per output, block=512 (NOT 1024: a 1024-thread block
// allows only one resident CTA/SM, forcing 256 CTAs into two serial waves on
// 148 SMs — measured in R1). With 512 threads, 2 CTAs co-reside per SM and the
// whole grid runs in one wave. Each thread issues 2 independent scattered W
// loads; finalize (bias + activation select) is inline, no cross-CTA protocol.

#define BLOCK 512

__global__ void __launch_bounds__(BLOCK, 2)
custom_network_kernel(const float* __restrict__ in_vals,
                      const float* __restrict__ W,
                      const float* __restrict__ bias,
                      const int*   __restrict__ act_ids,
                      const int*   __restrict__ in_idx,
                      const int*   __restrict__ out_idx,
                      float*       __restrict__ out,
                      int n_in, long long N)
{
    const int j = __ldg(&out_idx[blockIdx.x]);   // output column (uniform/CTA)
    const int t = threadIdx.x;

    // Two independent loads per thread (rows t and t+BLOCK), both issued
    // before any FMA -> MLP=2 per thread, 32 warps/SM hide the L2/DRAM latency.
    float p0 = 0.0f, p1 = 0.0f;
    const int i0 = t;
    const int i1 = t + BLOCK;
    if (i0 < n_in) {
        const long long r0 = (long long)__ldg(&in_idx[i0]);
        p0 = __ldg(&in_vals[i0]) * __ldg(&W[r0 * N + (long long)j]);
    }
    if (i1 < n_in) {
        const long long r1 = (long long)__ldg(&in_idx[i1]);
        p1 = __ldg(&in_vals[i1]) * __ldg(&W[r1 * N + (long long)j]);
    }
    float p = p0 + p1;

    // Handle n_in > 2*BLOCK generically (no-op for n_in=1024).
    for (int i = t + 2 * BLOCK; i < n_in; i += BLOCK) {
        const long long r = (long long)__ldg(&in_idx[i]);
        p += __ldg(&in_vals[i]) * __ldg(&W[r * N + (long long)j]);
    }

    // Warp reduce, then cross-warp combine (16 warps).
    #pragma unroll
    for (int off = 16; off > 0; off >>= 1)
        p += __shfl_xor_sync(0xFFFFFFFFu, p, off);

    __shared__ float sm[BLOCK / 32];
    const int lane = t & 31;
    const int wid  = t >> 5;
    if (lane == 0) sm[wid] = p;
    __syncthreads();

    if (wid == 0) {
        float v = (lane < BLOCK / 32) ? sm[lane] : 0.0f;
        #pragma unroll
        for (int off = 8; off > 0; off >>= 1)
            v += __shfl_xor_sync(0xFFFFFFFFu, v, off);

        if (lane == 0) {
            const float total = v + __ldg(&bias[j]);
            const int   a     = __ldg(&act_ids[j]);
            const float relu  = fmaxf(total, 0.0f);
            const float ssign = total / (1.0f + fabsf(total));
            out[blockIdx.x] = (a == 1) ? relu : ((a == 2) ? ssign : total);
        }
    }
}

extern "C" void kernel_launch(void* const* d_in, const int* in_sizes, int n_in_args,
                              void* d_out, int out_size)
{
    const float* in_vals = (const float*)d_in[0];
    const float* W       = (const float*)d_in[1];
    const float* bias    = (const float*)d_in[2];
    const int*   act_ids = (const int*)  d_in[3];
    const int*   in_idx  = (const int*)  d_in[4];
    const int*   out_idx = (const int*)  d_in[5];
    float*       out     = (float*)      d_out;

    const int n_in = in_sizes[0];                 // 1024
    const long long N = (long long)in_sizes[2];   // 16384 (bias length)

    custom_network_kernel<<<out_size, BLOCK>>>(
        in_vals, W, bias, act_ids, in_idx, out_idx, out, n_in, N);
}